// round 1
// baseline (speedup 1.0000x reference)
#include <cuda_runtime.h>
#include <cstdint>

#define NB 4
#define NN 4096
#define ND 16
#define KK 10
#define TT 12
#define RPB 16          // rows per block (kernel 2)
#define TILE_M 256      // m-tile held in shared
#define CAP 64          // per-row candidate buffer capacity
#define FULLM 0xFFFFFFFFu

// state embeddings: [B][N][D]
__device__ float g_emb[NB * NN * ND];

// ---------------------------------------------------------------------------
// Kernel 1: state_emb[b,n,j] = tanh(x[b,T-1,n,0] * W[j] + bfc[j])
// ---------------------------------------------------------------------------
__global__ void emb_kernel(const float* __restrict__ x,
                           const float* __restrict__ W,
                           const float* __restrict__ bfc) {
    int i = blockIdx.x * blockDim.x + threadIdx.x;   // 0 .. B*N-1
    if (i >= NB * NN) return;
    int b = i >> 12;
    int n = i & (NN - 1);
    float xv = x[((size_t)b * TT + (TT - 1)) * NN + n];
    float4* dst = reinterpret_cast<float4*>(&g_emb[(size_t)i * ND]);
#pragma unroll
    for (int j4 = 0; j4 < 4; j4++) {
        float4 o;
        o.x = tanhf(fmaf(xv, W[j4 * 4 + 0], bfc[j4 * 4 + 0]));
        o.y = tanhf(fmaf(xv, W[j4 * 4 + 1], bfc[j4 * 4 + 1]));
        o.z = tanhf(fmaf(xv, W[j4 * 4 + 2], bfc[j4 * 4 + 2]));
        o.w = tanhf(fmaf(xv, W[j4 * 4 + 3], bfc[j4 * 4 + 3]));
        dst[j4] = o;
    }
}

// ---------------------------------------------------------------------------
// 16-term dot, fixed summation order
// ---------------------------------------------------------------------------
__device__ __forceinline__ float dot16(const float* e, float4 q0, float4 q1,
                                       float4 q2, float4 q3) {
    float s0 = fmaf(e[3], q0.w, fmaf(e[2], q0.z, fmaf(e[1], q0.y, e[0] * q0.x)));
    float s1 = fmaf(e[7], q1.w, fmaf(e[6], q1.z, fmaf(e[5], q1.y, e[4] * q1.x)));
    float s2 = fmaf(e[11], q2.w, fmaf(e[10], q2.z, fmaf(e[9], q2.y, e[8] * q2.x)));
    float s3 = fmaf(e[15], q3.w, fmaf(e[14], q3.z, fmaf(e[13], q3.y, e[12] * q3.x)));
    return (s0 + s1) + (s2 + s3);
}

__device__ __forceinline__ float val_of(unsigned long long e) {
    return __uint_as_float((unsigned)(e >> 32));
}

// Warp-collective: select top-KK of cand[0..cnt) (packed (valbits<<32)|idx,
// all nonzero entries unique), write sorted-descending into topout[0..KK),
// keep them in cand[0..KK), set cnt=KK, return new threshold (value of 10th).
__device__ float warp_select(unsigned long long* cand, int& cnt,
                             unsigned long long* topout, int lane) {
    for (int k = 0; k < KK; k++) {
        unsigned long long best = 0ULL;
        for (int i = lane; i < cnt; i += 32) {
            unsigned long long c = cand[i];
            if (c > best) best = c;
        }
#pragma unroll
        for (int off = 16; off; off >>= 1) {
            unsigned long long o = __shfl_xor_sync(FULLM, best, off);
            if (o > best) best = o;
        }
        if (best != 0ULL) {
            int fi = -1;
            for (int i = lane; i < cnt; i += 32) {
                if (cand[i] == best) { fi = i; break; }
            }
            unsigned mm = __ballot_sync(FULLM, fi >= 0);
            if (lane == (int)(__ffs(mm) - 1)) cand[fi] = 0ULL;
        }
        if (lane == 0) topout[k] = best;
    }
    __syncwarp();
    if (lane < KK) cand[lane] = topout[lane];
    cnt = KK;
    float thr = val_of(topout[KK - 1]);
    __syncwarp();
    return thr;
}

// ---------------------------------------------------------------------------
// Kernel 2: fused A_dyn row computation + top-10 + softmax consts + output
// Grid: (NN/RPB, NB), 256 threads. Warp g owns rows 2g, 2g+1 of the tile.
// ---------------------------------------------------------------------------
__global__ __launch_bounds__(256, 2) void fused_kernel(
    const float* __restrict__ Aphys,
    const float* __restrict__ alpha_p,
    float* __restrict__ out) {
    __shared__ float4 tile4[TILE_M * 5];                 // swizzle stride 5 f4
    __shared__ unsigned long long cand[RPB][CAP];
    __shared__ unsigned long long shtop[RPB][KK];
    __shared__ float sh_emb[RPB * ND];
    __shared__ float sh_base[RPB], sh_c1[RPB], sh_vmax[RPB];

    const int t = threadIdx.x;
    const int lane = t & 31;
    const int g = t >> 5;
    const int b = blockIdx.y;
    const int n0 = blockIdx.x * RPB;

    const float alpha = *alpha_p;
    const float a = 1.f / (1.f + __expf(-alpha));
    const float oma = 1.f - a;

    // load this block's row embeddings
    sh_emb[t] = g_emb[((size_t)b * NN + n0 + (t >> 4)) * ND + (t & 15)];
    __syncthreads();

    float ea[ND], eb[ND];
    const int rA = 2 * g, rB = 2 * g + 1;
#pragma unroll
    for (int j = 0; j < ND; j++) {
        ea[j] = sh_emb[rA * ND + j];
        eb[j] = sh_emb[rB * ND + j];
    }

    int cntA = 0, cntB = 0;
    float thrA = 0.f, thrB = 0.f;

    const float4* emb4 = reinterpret_cast<const float4*>(g_emb) + (size_t)b * NN * 4;

    for (int tile = 0; tile < NN / TILE_M; tile++) {
        __syncthreads();
        {   // cooperative tile load: thread t loads emb row (tile*256 + t)
            const float4* src = emb4 + (size_t)(tile * TILE_M + t) * 4;
            float4 v0 = src[0], v1 = src[1], v2 = src[2], v3 = src[3];
            tile4[t * 5 + 0] = v0;
            tile4[t * 5 + 1] = v1;
            tile4[t * 5 + 2] = v2;
            tile4[t * 5 + 3] = v3;
        }
        __syncthreads();

#pragma unroll
        for (int it = 0; it < TILE_M / 32; it++) {
            int ml = it * 32 + lane;
            float4 q0 = tile4[ml * 5 + 0];
            float4 q1 = tile4[ml * 5 + 1];
            float4 q2 = tile4[ml * 5 + 2];
            float4 q3 = tile4[ml * 5 + 3];
            float sA = dot16(ea, q0, q1, q2, q3);
            float sB = dot16(eb, q0, q1, q2, q3);
            int m = tile * TILE_M + ml;

            // row A candidate filter
            {
                bool p = sA > thrA;
                unsigned msk = __ballot_sync(FULLM, p);
                if (cntA + __popc(msk) > CAP) {
                    thrA = warp_select(cand[rA], cntA, shtop[rA], lane);
                    p = sA > thrA;
                    msk = __ballot_sync(FULLM, p);
                }
                if (p) {
                    int pos = cntA + __popc(msk & ((1u << lane) - 1));
                    cand[rA][pos] =
                        ((unsigned long long)__float_as_uint(sA) << 32) | (unsigned)m;
                }
                cntA += __popc(msk);
            }
            // row B candidate filter
            {
                bool p = sB > thrB;
                unsigned msk = __ballot_sync(FULLM, p);
                if (cntB + __popc(msk) > CAP) {
                    thrB = warp_select(cand[rB], cntB, shtop[rB], lane);
                    p = sB > thrB;
                    msk = __ballot_sync(FULLM, p);
                }
                if (p) {
                    int pos = cntB + __popc(msk & ((1u << lane) - 1));
                    cand[rB][pos] =
                        ((unsigned long long)__float_as_uint(sB) << 32) | (unsigned)m;
                }
                cntB += __popc(msk);
            }
        }
    }

    // final top-10 per row
    warp_select(cand[rA], cntA, shtop[rA], lane);
    warp_select(cand[rB], cntB, shtop[rB], lane);

    // per-row softmax constants (lane 0 of each warp, both rows)
    if (lane == 0) {
#pragma unroll
        for (int rr = 0; rr < 2; rr++) {
            int r = rA + rr;
            float vmax = val_of(shtop[r][0]);
            float s = 0.f;
#pragma unroll
            for (int k = 0; k < KK; k++) s += __expf(val_of(shtop[r][k]) - vmax);
            float S = s + (float)(NN - KK) * __expf(-vmax);
            float c1 = oma / S;
            sh_c1[r] = c1;
            sh_vmax[r] = vmax;
            sh_base[r] = c1 * __expf(-vmax);
        }
    }
    __syncthreads();

    // Phase 3: write out = a*A_phys + base (all m), fully coalesced
    const float4* ap_base = reinterpret_cast<const float4*>(Aphys);
    float4* out4 = reinterpret_cast<float4*>(out) + (size_t)b * NN * (NN / 4);
    for (int r = 0; r < RPB; r++) {
        int row = n0 + r;
        float base = sh_base[r];
        const float4* ap = ap_base + (size_t)row * (NN / 4);
        float4* op = out4 + (size_t)row * (NN / 4);
        for (int i = t; i < NN / 4; i += 256) {
            float4 v = ap[i];
            float4 o;
            o.x = fmaf(a, v.x, base);
            o.y = fmaf(a, v.y, base);
            o.z = fmaf(a, v.z, base);
            o.w = fmaf(a, v.w, base);
            op[i] = o;
        }
    }
    __syncthreads();

    // Phase 4: scatter fix-ups for the K top entries (skip zero placeholders)
    if (t < RPB * KK) {
        int r = t / KK, k = t - r * KK;
        unsigned long long e = shtop[r][k];
        if (e != 0ULL) {
            unsigned idx = (unsigned)e;
            float v = val_of(e);
            int row = n0 + r;
            float pv = Aphys[(size_t)row * NN + idx];
            out[((size_t)b * NN + row) * NN + idx] =
                fmaf(a, pv, sh_c1[r] * __expf(v - sh_vmax[r]));
        }
    }
}

// ---------------------------------------------------------------------------
extern "C" void kernel_launch(void* const* d_in, const int* in_sizes, int n_in,
                              void* d_out, int out_size) {
    const float* x     = (const float*)d_in[0];
    const float* Aphys = (const float*)d_in[1];
    const float* Wfc   = (const float*)d_in[2];
    const float* bfc   = (const float*)d_in[3];
    const float* alpha = (const float*)d_in[4];
    float* out = (float*)d_out;

    emb_kernel<<<(NB * NN + 255) / 256, 256>>>(x, Wfc, bfc);
    dim3 grid(NN / RPB, NB);
    fused_kernel<<<grid, 256>>>(Aphys, alpha, out);
}

// round 2
// speedup vs baseline: 1.9715x; 1.9715x over previous
#include <cuda_runtime.h>
#include <cstdint>

#define NB 4
#define NN 4096
#define ND 16
#define KK 10
#define TT 12
#define RPB 16          // rows per block
#define TILE_M 256      // m-tile held in shared
#define FULLM 0xFFFFFFFFu

typedef unsigned long long u64;

// state embeddings: [B][N][D]
__device__ float g_emb[NB * NN * ND];

// ---------------------------------------------------------------------------
// Kernel 1: state_emb[b,n,j] = tanh(x[b,T-1,n,0] * W[j] + bfc[j])
// ---------------------------------------------------------------------------
__global__ void emb_kernel(const float* __restrict__ x,
                           const float* __restrict__ W,
                           const float* __restrict__ bfc) {
    int i = blockIdx.x * blockDim.x + threadIdx.x;   // 0 .. B*N-1
    if (i >= NB * NN) return;
    int b = i >> 12;
    int n = i & (NN - 1);
    float xv = x[((size_t)b * TT + (TT - 1)) * NN + n];
    float4* dst = reinterpret_cast<float4*>(&g_emb[(size_t)i * ND]);
#pragma unroll
    for (int j4 = 0; j4 < 4; j4++) {
        float4 o;
        o.x = tanhf(fmaf(xv, W[j4 * 4 + 0], bfc[j4 * 4 + 0]));
        o.y = tanhf(fmaf(xv, W[j4 * 4 + 1], bfc[j4 * 4 + 1]));
        o.z = tanhf(fmaf(xv, W[j4 * 4 + 2], bfc[j4 * 4 + 2]));
        o.w = tanhf(fmaf(xv, W[j4 * 4 + 3], bfc[j4 * 4 + 3]));
        dst[j4] = o;
    }
}

// ---------------------------------------------------------------------------
// 16-term dot, fixed summation order (identical to round-1 passing version)
// ---------------------------------------------------------------------------
__device__ __forceinline__ float dot16(const float* e, float4 q0, float4 q1,
                                       float4 q2, float4 q3) {
    float s0 = fmaf(e[3], q0.w, fmaf(e[2], q0.z, fmaf(e[1], q0.y, e[0] * q0.x)));
    float s1 = fmaf(e[7], q1.w, fmaf(e[6], q1.z, fmaf(e[5], q1.y, e[4] * q1.x)));
    float s2 = fmaf(e[11], q2.w, fmaf(e[10], q2.z, fmaf(e[9], q2.y, e[8] * q2.x)));
    float s3 = fmaf(e[15], q3.w, fmaf(e[14], q3.z, fmaf(e[13], q3.y, e[12] * q3.x)));
    return (s0 + s1) + (s2 + s3);
}

__device__ __forceinline__ float val_of(u64 e) {
    return __uint_as_float((unsigned)(e >> 32));
}

// Branch-free sorted-descending insert of p into r[0..9]. Caller guards p > r[9].
__device__ __forceinline__ void insert10(u64* r, u64 p) {
#pragma unroll
    for (int i = 9; i >= 1; i--) {
        u64 hi = r[i - 1];
        u64 lo = r[i];
        r[i] = (p > hi) ? hi : ((p > lo) ? p : lo);
    }
    if (p > r[0]) r[0] = p;
}

// Merge 32 lanes' sorted-desc top-10 (register arrays) into shtop[0..9].
// Packed values are unique except for 0 placeholders.
__device__ __forceinline__ void warp_merge(u64* top, u64* shtop, int lane) {
#pragma unroll
    for (int k = 0; k < KK; k++) {
        u64 h = top[0];
        u64 mx = h;
#pragma unroll
        for (int off = 16; off; off >>= 1) {
            u64 o = __shfl_xor_sync(FULLM, mx, off);
            if (o > mx) mx = o;
        }
        if (lane == 0) shtop[k] = mx;
        bool mine = (h == mx) && (mx != 0ULL);
        unsigned msk = __ballot_sync(FULLM, mine);
        if (msk && lane == (int)(__ffs(msk) - 1)) {
            // pop head: shift up
#pragma unroll
            for (int i = 0; i < 9; i++) top[i] = top[i + 1];
            top[9] = 0ULL;
        }
    }
}

// ---------------------------------------------------------------------------
// Kernel 2: fused A_dyn rows + exact top-10 + softmax consts + output
// Grid: (NN/RPB, NB), 256 threads. Warp g owns rows 2g, 2g+1.
// ---------------------------------------------------------------------------
__global__ __launch_bounds__(256, 2) void fused_kernel(
    const float* __restrict__ Aphys,
    const float* __restrict__ alpha_p,
    float* __restrict__ out) {
    __shared__ float4 tile4[TILE_M * 5];     // stride-5 float4 -> LDS.128 conflict-free
    __shared__ u64 shtop[RPB][KK];
    __shared__ float sh_emb[RPB * ND];
    __shared__ float sh_base[RPB], sh_c1[RPB], sh_vmax[RPB];

    const int t = threadIdx.x;
    const int lane = t & 31;
    const int g = t >> 5;
    const int b = blockIdx.y;
    const int n0 = blockIdx.x * RPB;

    const float alpha = *alpha_p;
    const float a = 1.f / (1.f + expf(-alpha));
    const float oma = 1.f - a;

    // load this block's row embeddings
    sh_emb[t] = g_emb[((size_t)b * NN + n0 + (t >> 4)) * ND + (t & 15)];
    __syncthreads();

    float ea[ND], eb[ND];
    const int rA = 2 * g, rB = 2 * g + 1;
#pragma unroll
    for (int j = 0; j < ND; j++) {
        ea[j] = sh_emb[rA * ND + j];
        eb[j] = sh_emb[rB * ND + j];
    }

    u64 topA[KK], topB[KK];
#pragma unroll
    for (int k = 0; k < KK; k++) { topA[k] = 0ULL; topB[k] = 0ULL; }

    const float4* emb4 = reinterpret_cast<const float4*>(g_emb) + (size_t)b * NN * 4;

    for (int tile = 0; tile < NN / TILE_M; tile++) {
        __syncthreads();
        {   // cooperative tile load: thread t stages emb row (tile*256 + t)
            const float4* src = emb4 + (size_t)(tile * TILE_M + t) * 4;
            float4 v0 = src[0], v1 = src[1], v2 = src[2], v3 = src[3];
            tile4[t * 5 + 0] = v0;
            tile4[t * 5 + 1] = v1;
            tile4[t * 5 + 2] = v2;
            tile4[t * 5 + 3] = v3;
        }
        __syncthreads();

#pragma unroll
        for (int it = 0; it < TILE_M / 32; it++) {
            int ml = it * 32 + lane;
            float4 q0 = tile4[ml * 5 + 0];
            float4 q1 = tile4[ml * 5 + 1];
            float4 q2 = tile4[ml * 5 + 2];
            float4 q3 = tile4[ml * 5 + 3];
            float sA = dot16(ea, q0, q1, q2, q3);
            float sB = dot16(eb, q0, q1, q2, q3);
            unsigned m = (unsigned)(tile * TILE_M + ml);

            if (sA > 0.f) {
                u64 p = ((u64)__float_as_uint(sA) << 32) | m;
                if (p > topA[KK - 1]) insert10(topA, p);
            }
            if (sB > 0.f) {
                u64 p = ((u64)__float_as_uint(sB) << 32) | m;
                if (p > topB[KK - 1]) insert10(topB, p);
            }
        }
    }

    // exact warp-wide top-10 per row
    warp_merge(topA, shtop[rA], lane);
    warp_merge(topB, shtop[rB], lane);

    // per-row softmax constants (lane 0 of each warp handles its 2 rows)
    if (lane == 0) {
#pragma unroll
        for (int rr = 0; rr < 2; rr++) {
            int r = rA + rr;
            float vmax = val_of(shtop[r][0]);   // >= 0
            float s = 0.f;
#pragma unroll
            for (int k = 0; k < KK; k++) s += expf(val_of(shtop[r][k]) - vmax);
            float S = s + (float)(NN - KK) * expf(-vmax);
            float c1 = oma / S;
            sh_c1[r] = c1;
            sh_vmax[r] = vmax;
            sh_base[r] = c1 * expf(-vmax);
        }
    }
    __syncthreads();

    // Phase 3: out = a*A_phys + base for all m (coalesced float4)
    const float4* ap_base = reinterpret_cast<const float4*>(Aphys);
    float4* out4 = reinterpret_cast<float4*>(out) + (size_t)b * NN * (NN / 4);
    for (int r = 0; r < RPB; r++) {
        int row = n0 + r;
        float base = sh_base[r];
        const float4* ap = ap_base + (size_t)row * (NN / 4);
        float4* op = out4 + (size_t)row * (NN / 4);
#pragma unroll 4
        for (int i = t; i < NN / 4; i += 256) {
            float4 v = ap[i];
            float4 o;
            o.x = fmaf(a, v.x, base);
            o.y = fmaf(a, v.y, base);
            o.z = fmaf(a, v.z, base);
            o.w = fmaf(a, v.w, base);
            op[i] = o;
        }
    }
    __syncthreads();

    // Phase 4: scatter fix-ups for top-K entries (skip zero placeholders)
    if (t < RPB * KK) {
        int r = t / KK, k = t - r * KK;
        u64 e = shtop[r][k];
        if (e != 0ULL) {
            unsigned idx = (unsigned)e;
            float v = val_of(e);
            int row = n0 + r;
            float pv = Aphys[(size_t)row * NN + idx];
            out[((size_t)b * NN + row) * NN + idx] =
                fmaf(a, pv, sh_c1[r] * expf(v - sh_vmax[r]));
        }
    }
}

// ---------------------------------------------------------------------------
extern "C" void kernel_launch(void* const* d_in, const int* in_sizes, int n_in,
                              void* d_out, int out_size) {
    const float* x     = (const float*)d_in[0];
    const float* Aphys = (const float*)d_in[1];
    const float* Wfc   = (const float*)d_in[2];
    const float* bfc   = (const float*)d_in[3];
    const float* alpha = (const float*)d_in[4];
    float* out = (float*)d_out;

    emb_kernel<<<(NB * NN + 255) / 256, 256>>>(x, Wfc, bfc);
    dim3 grid(NN / RPB, NB);
    fused_kernel<<<grid, 256>>>(Aphys, alpha, out);
}

// round 3
// speedup vs baseline: 3.0447x; 1.5443x over previous
#include <cuda_runtime.h>
#include <cstdint>

#define NB 4
#define NN 4096
#define ND 16
#define KK 10
#define TT 12
#define RPB 16          // rows per block
#define TILE_M 256      // m-tile held in shared
#define FULLM 0xFFFFFFFFu

typedef unsigned long long u64;

// state embeddings: [B][N][D]
__device__ float g_emb[NB * NN * ND];

// ---------------------------------------------------------------------------
// f32x2 packed helpers (Blackwell FFMA2 path, PTX-only)
// ---------------------------------------------------------------------------
__device__ __forceinline__ u64 mul2(u64 a, u64 b) {
    u64 d; asm("mul.rn.f32x2 %0, %1, %2;" : "=l"(d) : "l"(a), "l"(b)); return d;
}
__device__ __forceinline__ u64 fma2(u64 a, u64 b, u64 c) {
    u64 d; asm("fma.rn.f32x2 %0, %1, %2, %3;" : "=l"(d) : "l"(a), "l"(b), "l"(c)); return d;
}
__device__ __forceinline__ u64 add2(u64 a, u64 b) {
    u64 d; asm("add.rn.f32x2 %0, %1, %2;" : "=l"(d) : "l"(a), "l"(b)); return d;
}
__device__ __forceinline__ float red2(u64 a) {
    unsigned lo, hi;
    asm("mov.b64 {%0, %1}, %2;" : "=r"(lo), "=r"(hi) : "l"(a));
    return __uint_as_float(lo) + __uint_as_float(hi);
}
__device__ __forceinline__ float val_of(u64 e) {
    return __uint_as_float((unsigned)(e >> 32));
}

// ---------------------------------------------------------------------------
// Kernel 1: state_emb[b,n,j] = tanh(x[b,T-1,n,0] * W[j] + bfc[j])
// ---------------------------------------------------------------------------
__global__ void emb_kernel(const float* __restrict__ x,
                           const float* __restrict__ W,
                           const float* __restrict__ bfc) {
    int i = blockIdx.x * blockDim.x + threadIdx.x;   // 0 .. B*N-1
    if (i >= NB * NN) return;
    int b = i >> 12;
    int n = i & (NN - 1);
    float xv = x[((size_t)b * TT + (TT - 1)) * NN + n];
    float4* dst = reinterpret_cast<float4*>(&g_emb[(size_t)i * ND]);
#pragma unroll
    for (int j4 = 0; j4 < 4; j4++) {
        float4 o;
        o.x = tanhf(fmaf(xv, W[j4 * 4 + 0], bfc[j4 * 4 + 0]));
        o.y = tanhf(fmaf(xv, W[j4 * 4 + 1], bfc[j4 * 4 + 1]));
        o.z = tanhf(fmaf(xv, W[j4 * 4 + 2], bfc[j4 * 4 + 2]));
        o.w = tanhf(fmaf(xv, W[j4 * 4 + 3], bfc[j4 * 4 + 3]));
        dst[j4] = o;
    }
}

// ---------------------------------------------------------------------------
// Warp-collective insert of candidates (ballot mask msk, per-lane score s)
// into the distributed sorted top-10 (lane k holds k-th largest, k<10).
// Candidate index = mbase + src_lane. Stale candidates (pos==10) are no-ops.
// ---------------------------------------------------------------------------
__device__ __forceinline__ void warp_insert(u64& ent, unsigned msk, float s,
                                            unsigned mbase, int lane) {
    while (msk) {
        int src = __ffs(msk) - 1;
        msk &= msk - 1;
        float pv = __shfl_sync(FULLM, s, src);
        u64 p = ((u64)__float_as_uint(pv) << 32) | (u64)(mbase + src);
        unsigned gmask = __ballot_sync(FULLM, ent > p) & 0x3FFu;
        int pos = __popc(gmask);
        u64 shifted = __shfl_up_sync(FULLM, ent, 1);
        if (lane >= pos && lane < KK) ent = (lane == pos) ? p : shifted;
    }
}

// ---------------------------------------------------------------------------
// Kernel 2: fused A_dyn rows + exact warp-wide top-10 + softmax + output
// Grid: (NN/RPB, NB), 256 threads. Warp g owns rows 2g, 2g+1.
// ---------------------------------------------------------------------------
__global__ __launch_bounds__(256, 2) void fused_kernel(
    const float* __restrict__ Aphys,
    const float* __restrict__ alpha_p,
    float* __restrict__ out) {
    __shared__ float4 tile4[TILE_M * 5];     // stride-5 float4 -> conflict-free
    __shared__ u64 shtop[RPB][KK];
    __shared__ float sh_emb[RPB * ND];
    __shared__ float sh_base[RPB], sh_c1[RPB], sh_vmax[RPB];

    const int t = threadIdx.x;
    const int lane = t & 31;
    const int g = t >> 5;
    const int b = blockIdx.y;
    const int n0 = blockIdx.x * RPB;

    const float alpha = *alpha_p;
    const float a = 1.f / (1.f + expf(-alpha));
    const float oma = 1.f - a;

    // load this block's row embeddings
    sh_emb[t] = g_emb[((size_t)b * NN + n0 + (t >> 4)) * ND + (t & 15)];
    __syncthreads();

    // packed (even-d, odd-d) embedding pairs for this warp's 2 rows
    const int rA = 2 * g, rB = 2 * g + 1;
    u64 eA[8], eB[8];
    {
        const u64* pa = reinterpret_cast<const u64*>(&sh_emb[rA * ND]);
        const u64* pb = reinterpret_cast<const u64*>(&sh_emb[rB * ND]);
#pragma unroll
        for (int j = 0; j < 8; j++) { eA[j] = pa[j]; eB[j] = pb[j]; }
    }

    u64 entA = 0ULL, entB = 0ULL;     // distributed top-10 (lanes 0..9)
    float thrA = 0.f, thrB = 0.f;     // value of current 10th largest

    const float4* emb4 = reinterpret_cast<const float4*>(g_emb) + (size_t)b * NN * 4;

    for (int tile = 0; tile < NN / TILE_M; tile++) {
        __syncthreads();
        {   // cooperative stage: thread t loads emb row (tile*256 + t)
            const float4* src = emb4 + (size_t)(tile * TILE_M + t) * 4;
            float4 v0 = src[0], v1 = src[1], v2 = src[2], v3 = src[3];
            tile4[t * 5 + 0] = v0;
            tile4[t * 5 + 1] = v1;
            tile4[t * 5 + 2] = v2;
            tile4[t * 5 + 3] = v3;
        }
        __syncthreads();

#pragma unroll
        for (int it = 0; it < TILE_M / 32; it++) {
            const int ml = it * 32 + lane;
            const ulonglong2* q =
                reinterpret_cast<const ulonglong2*>(tile4 + ml * 5);
            ulonglong2 q0 = q[0], q1 = q[1], q2 = q[2], q3 = q[3];

            u64 aP = mul2(eA[0], q0.x);
            u64 aQ = mul2(eA[1], q0.y);
            u64 bP = mul2(eB[0], q0.x);
            u64 bQ = mul2(eB[1], q0.y);
            aP = fma2(eA[2], q1.x, aP);  aQ = fma2(eA[3], q1.y, aQ);
            bP = fma2(eB[2], q1.x, bP);  bQ = fma2(eB[3], q1.y, bQ);
            aP = fma2(eA[4], q2.x, aP);  aQ = fma2(eA[5], q2.y, aQ);
            bP = fma2(eB[4], q2.x, bP);  bQ = fma2(eB[5], q2.y, bQ);
            aP = fma2(eA[6], q3.x, aP);  aQ = fma2(eA[7], q3.y, aQ);
            bP = fma2(eB[6], q3.x, bP);  bQ = fma2(eB[7], q3.y, bQ);
            float sA = red2(add2(aP, aQ));
            float sB = red2(add2(bP, bQ));

            const unsigned mbase = (unsigned)(tile * TILE_M + it * 32);
            unsigned mskA = __ballot_sync(FULLM, sA > thrA);
            if (mskA) {
                warp_insert(entA, mskA, sA, mbase, lane);
                thrA = __uint_as_float(
                    (unsigned)(__shfl_sync(FULLM, entA, KK - 1) >> 32));
            }
            unsigned mskB = __ballot_sync(FULLM, sB > thrB);
            if (mskB) {
                warp_insert(entB, mskB, sB, mbase, lane);
                thrB = __uint_as_float(
                    (unsigned)(__shfl_sync(FULLM, entB, KK - 1) >> 32));
            }
        }
    }

    // publish warp-wide sorted top-10 (already distributed; no merge needed)
    if (lane < KK) {
        shtop[rA][lane] = entA;
        shtop[rB][lane] = entB;
    }
    __syncwarp();

    // per-row softmax constants (lane 0 of each warp handles its 2 rows)
    if (lane == 0) {
#pragma unroll
        for (int rr = 0; rr < 2; rr++) {
            int r = rA + rr;
            float vmax = val_of(shtop[r][0]);   // >= 0
            float s = 0.f;
#pragma unroll
            for (int k = 0; k < KK; k++) s += expf(val_of(shtop[r][k]) - vmax);
            float S = s + (float)(NN - KK) * expf(-vmax);
            float c1 = oma / S;
            sh_c1[r] = c1;
            sh_vmax[r] = vmax;
            sh_base[r] = c1 * expf(-vmax);
        }
    }
    __syncthreads();

    // Phase 3: out = a*A_phys + base for all m (coalesced float4, streaming st)
    const float4* ap_base = reinterpret_cast<const float4*>(Aphys);
    float4* out4 = reinterpret_cast<float4*>(out) + (size_t)b * NN * (NN / 4);
    for (int r = 0; r < RPB; r++) {
        int row = n0 + r;
        float base = sh_base[r];
        const float4* ap = ap_base + (size_t)row * (NN / 4);
        float4* op = out4 + (size_t)row * (NN / 4);
#pragma unroll
        for (int u = 0; u < (NN / 4) / 256; u++) {
            int i = u * 256 + t;
            float4 v = ap[i];
            float4 o;
            o.x = fmaf(a, v.x, base);
            o.y = fmaf(a, v.y, base);
            o.z = fmaf(a, v.z, base);
            o.w = fmaf(a, v.w, base);
            __stcs(&op[i], o);
        }
    }
    __syncthreads();

    // Phase 4: scatter fix-ups for top-K entries (skip zero placeholders)
    if (t < RPB * KK) {
        int r = t / KK, k = t - r * KK;
        u64 e = shtop[r][k];
        if (e != 0ULL) {
            unsigned idx = (unsigned)e;
            float v = val_of(e);
            int row = n0 + r;
            float pv = Aphys[(size_t)row * NN + idx];
            out[((size_t)b * NN + row) * NN + idx] =
                fmaf(a, pv, sh_c1[r] * expf(v - sh_vmax[r]));
        }
    }
}

// ---------------------------------------------------------------------------
extern "C" void kernel_launch(void* const* d_in, const int* in_sizes, int n_in,
                              void* d_out, int out_size) {
    const float* x     = (const float*)d_in[0];
    const float* Aphys = (const float*)d_in[1];
    const float* Wfc   = (const float*)d_in[2];
    const float* bfc   = (const float*)d_in[3];
    const float* alpha = (const float*)d_in[4];
    float* out = (float*)d_out;

    emb_kernel<<<(NB * NN + 255) / 256, 256>>>(x, Wfc, bfc);
    dim3 grid(NN / RPB, NB);
    fused_kernel<<<grid, 256>>>(Aphys, alpha, out);
}